// round 3
// baseline (speedup 1.0000x reference)
#include <cuda_runtime.h>

// Problem constants (fixed by setup_inputs): B=4, N=M=8192, D=3
constexpr int Bn = 4;
constexpr int Nn = 8192;
constexpr int Mn = 8192;

constexpr int TC    = 256;   // target chunk staged in shared
constexpr int R     = 8;     // source rows per thread
constexpr int NP    = R / 2; // packed row-pairs per thread
constexpr int T     = 128;   // threads per block
constexpr int ST    = T * R; // 1024 source rows per block
constexpr int NWARP = T / 32;

// Scratch: row mins [0, B*N), col mins [B*N, 2*B*N). Order-preserving uint keys.
__device__ unsigned g_minbuf[2 * Bn * Nn];

using u64 = unsigned long long;

// ---- packed f32x2 helpers (sm_103a) ----
__device__ __forceinline__ u64 pack2(float lo, float hi) {
    u64 d; asm("mov.b64 %0, {%1, %2};" : "=l"(d) : "f"(lo), "f"(hi)); return d;
}
__device__ __forceinline__ void unpack2(u64 v, float& lo, float& hi) {
    asm("mov.b64 {%0, %1}, %2;" : "=f"(lo), "=f"(hi) : "l"(v));
}
__device__ __forceinline__ u64 fma2(u64 a, u64 b, u64 c) {
    u64 d; asm("fma.rn.f32x2 %0, %1, %2, %3;" : "=l"(d) : "l"(a), "l"(b), "l"(c)); return d;
}
__device__ __forceinline__ u64 mul2(u64 a, u64 b) {
    u64 d; asm("mul.rn.f32x2 %0, %1, %2;" : "=l"(d) : "l"(a), "l"(b)); return d;
}

__device__ __forceinline__ unsigned fkey(float x) {
    unsigned u = __float_as_uint(x);
    return u ^ ((unsigned)((int)u >> 31) | 0x80000000u);  // order-preserving
}
__device__ __forceinline__ float funkey(unsigned k) {
    return (k & 0x80000000u) ? __uint_as_float(k & 0x7fffffffu)
                             : __uint_as_float(~k);
}

__global__ void init_minbuf() {
    int i = blockIdx.x * blockDim.x + threadIdx.x;
    uint4 v = make_uint4(~0u, ~0u, ~0u, ~0u);
    ((uint4*)g_minbuf)[i] = v;
}

__global__ __launch_bounds__(T, 8)
void chamfer_main(const float* __restrict__ src, const float* __restrict__ tgt) {
    __shared__ float4   tshA[TC];         // {x, x, y, y}  (pre-duplicated for f32x2)
    __shared__ float4   tshB[TC];         // {z, z, w, w}  with w = |t|^2
    __shared__ unsigned scolw[NWARP][TC]; // per-warp column min keys

    const int tid  = threadIdx.x;
    const int lane = tid & 31;
    const int w    = tid >> 5;
    const int b    = blockIdx.z;
    const int s0   = blockIdx.y * ST;
    const int t0   = blockIdx.x * TC;

    // Stage target chunk, components duplicated so LDS.128 yields ready f32x2 pairs
    for (int i = tid; i < TC; i += T) {
        const float* p = tgt + ((size_t)b * Mn + t0 + i) * 3;
        float x = p[0], y = p[1], z = p[2];
        float sq = fmaf(x, x, fmaf(y, y, z * z));
        tshA[i] = make_float4(x, x, y, y);
        tshB[i] = make_float4(z, z, sq, sq);
    }

    // This thread's R source rows, packed two per f32x2 register pair
    u64 sxp[NP], syp[NP], szp[NP], sqp[NP];
    float eminL[NP], eminH[NP];
    const float INF = __int_as_float(0x7f800000);
#pragma unroll
    for (int p = 0; p < NP; p++) {
        int r0 = s0 + tid + (2 * p) * T;
        int r1 = r0 + T;
        const float* p0 = src + ((size_t)b * Nn + r0) * 3;
        const float* p1 = src + ((size_t)b * Nn + r1) * 3;
        float x0 = p0[0], y0 = p0[1], z0 = p0[2];
        float x1 = p1[0], y1 = p1[1], z1 = p1[2];
        sxp[p] = pack2(x0, x1);
        syp[p] = pack2(y0, y1);
        szp[p] = pack2(z0, z1);
        sqp[p] = pack2(fmaf(x0, x0, fmaf(y0, y0, z0 * z0)),
                       fmaf(x1, x1, fmaf(y1, y1, z1 * z1)));
        eminL[p] = INF; eminH[p] = INF;
    }
    const u64 neg2 = pack2(-2.0f, -2.0f);
    __syncthreads();

    // Main sweep: packed math, 2 rows per instruction
#pragma unroll 2
    for (int j = 0; j < TC; j++) {
        float4 qa = tshA[j];
        float4 qb = tshB[j];
        u64 txx = pack2(qa.x, qa.y);  // folds into LDS.128 register pairs
        u64 tyy = pack2(qa.z, qa.w);
        u64 tzz = pack2(qb.x, qb.y);
        u64 tww = pack2(qb.z, qb.w);

        float fl[R];
#pragma unroll
        for (int p = 0; p < NP; p++) {
            u64 c2 = fma2(szp[p], tzz, fma2(syp[p], tyy, mul2(sxp[p], txx)));
            u64 e2 = fma2(c2, neg2, tww);     // |t|^2 - 2c  (row-min term)
            u64 f2 = fma2(c2, neg2, sqp[p]);  // |s|^2 - 2c  (col-min term)
            float el, eh; unpack2(e2, el, eh);
            eminL[p] = fminf(eminL[p], el);
            eminH[p] = fminf(eminH[p], eh);
            unpack2(f2, fl[2 * p], fl[2 * p + 1]);
        }
        // Tree-min over this thread's 8 rows
#pragma unroll
        for (int s = R / 2; s > 0; s >>= 1)
#pragma unroll
            for (int r = 0; r < s; r++) fl[r] = fminf(fl[r], fl[r + s]);
        // Single-instruction warp reduction on order-preserving key
        unsigned k = __reduce_min_sync(0xffffffffu, fkey(fl[0]));
        if (lane == 0) scolw[w][j] = k;
    }
    __syncthreads();

    // Flush column mins: d2 = |t|^2 + min_r(|s|^2 - 2c)
    for (int j = tid; j < TC; j += T) {
        unsigned m = min(min(scolw[0][j], scolw[1][j]),
                         min(scolw[2][j], scolw[3][j]));
        float d = tshB[j].w + funkey(m);
        atomicMin(&g_minbuf[Bn * Nn + b * Mn + t0 + j], fkey(d));
    }
    // Flush row mins: d2 = |s|^2 + min_j(|t|^2 - 2c)
#pragma unroll
    for (int p = 0; p < NP; p++) {
        float sql, sqh; unpack2(sqp[p], sql, sqh);
        atomicMin(&g_minbuf[b * Nn + s0 + tid + (2 * p) * T],     fkey(sql + eminL[p]));
        atomicMin(&g_minbuf[b * Nn + s0 + tid + (2 * p + 1) * T], fkey(sqh + eminH[p]));
    }
}

__global__ void final_reduce(float* out) {
    __shared__ float sh[1024];
    int tid = threadIdx.x;
    float s = 0.0f;
    // Vectorized, fixed traversal order -> deterministic
    const uint4* p4 = (const uint4*)g_minbuf;
    const int n4 = (2 * Bn * Nn) / 4;
#pragma unroll 4
    for (int i = tid; i < n4; i += 1024) {
        uint4 v = p4[i];
        s += funkey(v.x) + funkey(v.y) + funkey(v.z) + funkey(v.w);
    }
    sh[tid] = s;
    __syncthreads();
#pragma unroll
    for (int st = 512; st > 0; st >>= 1) {
        if (tid < st) sh[tid] += sh[tid + st];
        __syncthreads();
    }
    if (tid == 0)
        out[0] = sh[0] / (float)(Bn * Nn);  // (sum_rows + sum_cols) / (B*G)
}

extern "C" void kernel_launch(void* const* d_in, const int* in_sizes, int n_in,
                              void* d_out, int out_size) {
    const float* src = (const float*)d_in[0];  // (4, 8192, 3) fp32
    const float* tgt = (const float*)d_in[1];  // (4, 8192, 3) fp32
    float* out = (float*)d_out;

    init_minbuf<<<(2 * Bn * Nn) / (256 * 4), 256>>>();

    dim3 grid(Mn / TC, Nn / ST, Bn);  // (32, 8, 4) = 1024 blocks
    chamfer_main<<<grid, T>>>(src, tgt);

    final_reduce<<<1, 1024>>>(out);
}

// round 4
// speedup vs baseline: 1.7016x; 1.7016x over previous
#include <cuda_runtime.h>

// Problem constants (fixed by setup_inputs): B=4, N=M=8192, D=3
constexpr int Bn = 4;
constexpr int Nn = 8192;
constexpr int Mn = 8192;
constexpr int BN = Bn * Nn;  // 32768 (= Bn*Mn too)

constexpr int TC    = 256;   // target chunk staged in shared
constexpr int R     = 8;     // source rows per thread
constexpr int T     = 128;   // threads per block
constexpr int ST    = T * R; // 1024 source rows per block
constexpr int NWARP = T / 32;
constexpr int NBX   = Mn / TC;  // 32 target chunks
constexpr int NBY   = Nn / ST;  // 8 source tiles

// Partial-min scratch (written unconditionally every call -> no init needed)
__device__ float g_rowp[NBX * BN];   // [bx][b*Nn+row] : row min over cols of chunk bx
__device__ float g_colp[NBY * BN];   // [by][b*Mn+col] : col min over rows of tile by
__device__ float g_bsum[256];        // per-block partial sums from reduce stage

__device__ __forceinline__ unsigned fkey(float x) {
    unsigned u = __float_as_uint(x);
    return u ^ ((unsigned)((int)u >> 31) | 0x80000000u);  // order-preserving
}
__device__ __forceinline__ float funkey(unsigned k) {
    return (k & 0x80000000u) ? __uint_as_float(k & 0x7fffffffu)
                             : __uint_as_float(~k);
}
// FFMA with immediate multiplier 1.0 -> rt=1 imm-form, not demotable to FADD
__device__ __forceinline__ float fma1(float a, float c) {
    float d; asm("fma.rn.f32 %0, %1, 0f3F800000, %2;" : "=f"(d) : "f"(a), "f"(c));
    return d;
}

__global__ __launch_bounds__(T, 8)
void chamfer_main(const float* __restrict__ src, const float* __restrict__ tgt) {
    __shared__ float4   tsh[TC];          // target x,y,z,|t|^2
    __shared__ unsigned scolw[NWARP][TC]; // per-warp column min keys

    const int tid  = threadIdx.x;
    const int lane = tid & 31;
    const int w    = tid >> 5;
    const int bx   = blockIdx.x;
    const int by   = blockIdx.y;
    const int b    = blockIdx.z;
    const int s0   = by * ST;
    const int t0   = bx * TC;

    // Stage target chunk into shared (x, y, z, |t|^2)
    for (int i = tid; i < TC; i += T) {
        const float* p = tgt + ((size_t)b * Mn + t0 + i) * 3;
        float x = p[0], y = p[1], z = p[2];
        tsh[i] = make_float4(x, y, z, fmaf(x, x, fmaf(y, y, z * z)));
    }

    // Source rows: store NEGATED-DOUBLED coords so the dot chain seeds with t.w
    float sxn[R], syn[R], szn[R], sqs[R], emin[R];
    const float INF = __int_as_float(0x7f800000);
#pragma unroll
    for (int r = 0; r < R; r++) {
        int row = s0 + tid + r * T;
        const float* p = src + ((size_t)b * Nn + row) * 3;
        float x = p[0], y = p[1], z = p[2];
        sxn[r] = -2.0f * x; syn[r] = -2.0f * y; szn[r] = -2.0f * z;
        sqs[r] = fmaf(x, x, fmaf(y, y, z * z));
        emin[r] = INF;
    }
    __syncthreads();

    // Main sweep: 7 fma-pipe cycles per (row,col) pair
#pragma unroll 4
    for (int j = 0; j < TC; j++) {
        float4 t = tsh[j];  // broadcast LDS.128, conflict-free
        float fl[R];
#pragma unroll
        for (int r = 0; r < R; r++) {
            float e = fmaf(sxn[r], t.x, t.w);   // FFMA rt=2
            e = fmaf(syn[r], t.y, e);           // FFMA rt=2
            e = fmaf(szn[r], t.z, e);           // FFMA rt=2   e = |t|^2 - 2c
            emin[r] = fminf(emin[r], e);        // FMNMX (alu pipe)
            fl[r] = fma1(e, sqs[r]);            // FFMA-imm rt=1: g = d2 = e + |s|^2
        }
        // Tree-min over this thread's 8 rows (alu pipe)
#pragma unroll
        for (int s = R / 2; s > 0; s >>= 1)
#pragma unroll
            for (int r = 0; r < s; r++) fl[r] = fminf(fl[r], fl[r + s]);
        // Single-instruction warp reduction on order-preserving key
        unsigned k = __reduce_min_sync(0xffffffffu, fkey(fl[0]));
        if (lane == 0) scolw[w][j] = k;
    }
    __syncthreads();

    // Column partials: d2 min over this block's rows (already full d2 = g)
    for (int j = tid; j < TC; j += T) {
        unsigned m = min(min(scolw[0][j], scolw[1][j]),
                         min(scolw[2][j], scolw[3][j]));
        g_colp[by * BN + b * Mn + t0 + j] = funkey(m);
    }
    // Row partials: d2 = |s|^2 + min_j(|t|^2 - 2c)  (coalesced: consecutive tid -> row)
#pragma unroll
    for (int r = 0; r < R; r++)
        g_rowp[bx * BN + b * Nn + s0 + tid + r * T] = sqs[r] + emin[r];
}

// Stage 2: blocks 0..127 reduce rows, 128..255 reduce cols. Fixed-order sums.
__global__ void reduce_partials() {
    __shared__ float sh[256];
    const int tid = threadIdx.x;
    const int blk = blockIdx.x;
    float s;
    if (blk < 128) {
        int gr = blk * 256 + tid;  // one row per thread (128*256 = 32768)
        float m = g_rowp[gr];
#pragma unroll
        for (int k = 1; k < NBX; k++) m = fminf(m, g_rowp[k * BN + gr]);
        s = m;
    } else {
        int gc = (blk - 128) * 256 + tid;
        float m = g_colp[gc];
#pragma unroll
        for (int k = 1; k < NBY; k++) m = fminf(m, g_colp[k * BN + gc]);
        s = m;
    }
    sh[tid] = s;
    __syncthreads();
#pragma unroll
    for (int st = 128; st > 0; st >>= 1) {
        if (tid < st) sh[tid] += sh[tid + st];
        __syncthreads();
    }
    if (tid == 0) g_bsum[blk] = sh[0];
}

__global__ void final_sum(float* out) {
    __shared__ float sh[256];
    int tid = threadIdx.x;
    sh[tid] = g_bsum[tid];
    __syncthreads();
#pragma unroll
    for (int st = 128; st > 0; st >>= 1) {
        if (tid < st) sh[tid] += sh[tid + st];
        __syncthreads();
    }
    if (tid == 0)
        out[0] = sh[0] / (float)(Bn * Nn);  // (sum_rows + sum_cols) / (B*G)
}

extern "C" void kernel_launch(void* const* d_in, const int* in_sizes, int n_in,
                              void* d_out, int out_size) {
    const float* src = (const float*)d_in[0];  // (4, 8192, 3) fp32
    const float* tgt = (const float*)d_in[1];  // (4, 8192, 3) fp32
    float* out = (float*)d_out;

    dim3 grid(NBX, NBY, Bn);  // (32, 8, 4) = 1024 blocks
    chamfer_main<<<grid, T>>>(src, tgt);
    reduce_partials<<<256, 256>>>();
    final_sum<<<1, 256>>>(out);
}

// round 5
// speedup vs baseline: 1.7539x; 1.0307x over previous
#include <cuda_runtime.h>

// Problem constants (fixed by setup_inputs): B=4, N=M=8192, D=3
constexpr int Bn = 4;
constexpr int Nn = 8192;
constexpr int Mn = 8192;
constexpr int BN = Bn * Nn;  // 32768 (= Bn*Mn too)

constexpr int TC    = 256;   // target chunk staged in shared
constexpr int R     = 8;     // source rows per thread
constexpr int T     = 128;   // threads per block
constexpr int ST    = T * R; // 1024 source rows per block
constexpr int NWARP = T / 32;
constexpr int NBX   = Mn / TC;  // 32 target chunks
constexpr int NBY   = Nn / ST;  // 8 source tiles

// Partial-min scratch (written unconditionally every call -> no init needed)
__device__ float g_rowp[NBX * BN];   // [bx][b*Nn+row] : row min of d2 over chunk bx
__device__ float g_colp[NBY * BN];   // [by][b*Mn+col] : col min of d2 over tile by
__device__ float g_bsum[256];        // per-block partial sums from reduce stage

// FFMA with immediate multiplier 1.0 -> rt=1 imm-form, not demotable to FADD
__device__ __forceinline__ float fma1(float a, float c) {
    float d; asm("fma.rn.f32 %0, %1, 0f3F800000, %2;" : "=f"(d) : "f"(a), "f"(c));
    return d;
}

__global__ __launch_bounds__(T, 7)   // 7*148 >= 1024 blocks: still one wave, +regs slack
void chamfer_main(const float* __restrict__ src, const float* __restrict__ tgt) {
    __shared__ float4   tsh[TC];          // target x,y,z,|t|^2
    __shared__ unsigned scolw[NWARP][TC]; // per-warp column min (raw bits, nonneg)

    const int tid  = threadIdx.x;
    const int lane = tid & 31;
    const int w    = tid >> 5;
    const int bx   = blockIdx.x;
    const int by   = blockIdx.y;
    const int b    = blockIdx.z;
    const int s0   = by * ST;
    const int t0   = bx * TC;

    // Stage target chunk into shared (x, y, z, |t|^2)
    for (int i = tid; i < TC; i += T) {
        const float* p = tgt + ((size_t)b * Mn + t0 + i) * 3;
        float x = p[0], y = p[1], z = p[2];
        tsh[i] = make_float4(x, y, z, fmaf(x, x, fmaf(y, y, z * z)));
    }

    // Source rows: NEGATED-DOUBLED coords so the dot chain seeds with t.w
    float sxn[R], syn[R], szn[R], sqs[R], emin[R];
    const float INF = __int_as_float(0x7f800000);
#pragma unroll
    for (int r = 0; r < R; r++) {
        int row = s0 + tid + r * T;
        const float* p = src + ((size_t)b * Nn + row) * 3;
        float x = p[0], y = p[1], z = p[2];
        sxn[r] = -2.0f * x; syn[r] = -2.0f * y; szn[r] = -2.0f * z;
        sqs[r] = fmaf(x, x, fmaf(y, y, z * z));
        emin[r] = INF;
    }
    __syncthreads();

    // Main sweep: 7 fma-pipe cycles per (row,col) pair
#pragma unroll 4
    for (int j = 0; j < TC; j++) {
        float4 t = tsh[j];  // broadcast LDS.128, conflict-free
        float fl[R];
#pragma unroll
        for (int r = 0; r < R; r++) {
            float e = fmaf(sxn[r], t.x, t.w);   // FFMA rt=2
            e = fmaf(syn[r], t.y, e);           // FFMA rt=2
            e = fmaf(szn[r], t.z, e);           // FFMA rt=2   e = |t|^2 - 2c
            emin[r] = fminf(emin[r], e);        // FMNMX (alu pipe)
            fl[r] = fma1(e, sqs[r]);            // FFMA-imm rt=1: d2 = e + |s|^2
        }
        // Tree-min over this thread's 8 rows (alu pipe)
#pragma unroll
        for (int s = R / 2; s > 0; s >>= 1)
#pragma unroll
            for (int r = 0; r < s; r++) fl[r] = fminf(fl[r], fl[r + s]);
        // Clamp tiny negative rounding artifacts -> raw bits are order-preserving
        unsigned k = __reduce_min_sync(0xffffffffu,
                                       __float_as_uint(fmaxf(fl[0], 0.0f)));
        if (lane == 0) scolw[w][j] = k;
    }
    __syncthreads();

    // Column partials: min of d2 over this block's 1024 rows
    for (int j = tid; j < TC; j += T) {
        unsigned m = min(min(scolw[0][j], scolw[1][j]),
                         min(scolw[2][j], scolw[3][j]));
        g_colp[by * BN + b * Mn + t0 + j] = __uint_as_float(m);
    }
    // Row partials: d2 = |s|^2 + min_j(|t|^2 - 2c)  (coalesced)
#pragma unroll
    for (int r = 0; r < R; r++)
        g_rowp[bx * BN + b * Nn + s0 + tid + r * T] = sqs[r] + emin[r];
}

// Stage 2: blocks 0..127 reduce rows, 128..255 reduce cols. Fixed-order sums.
__global__ void reduce_partials() {
    __shared__ float sh[256];
    const int tid = threadIdx.x;
    const int blk = blockIdx.x;
    float s;
    if (blk < 128) {
        int gr = blk * 256 + tid;  // one row per thread (128*256 = 32768)
        float m = g_rowp[gr];
#pragma unroll
        for (int k = 1; k < NBX; k++) m = fminf(m, g_rowp[k * BN + gr]);
        s = m;
    } else {
        int gc = (blk - 128) * 256 + tid;
        float m = g_colp[gc];
#pragma unroll
        for (int k = 1; k < NBY; k++) m = fminf(m, g_colp[k * BN + gc]);
        s = m;
    }
    sh[tid] = s;
    __syncthreads();
#pragma unroll
    for (int st = 128; st > 0; st >>= 1) {
        if (tid < st) sh[tid] += sh[tid + st];
        __syncthreads();
    }
    if (tid == 0) g_bsum[blk] = sh[0];
}

__global__ void final_sum(float* out) {
    __shared__ float sh[256];
    int tid = threadIdx.x;
    sh[tid] = g_bsum[tid];
    __syncthreads();
#pragma unroll
    for (int st = 128; st > 0; st >>= 1) {
        if (tid < st) sh[tid] += sh[tid + st];
        __syncthreads();
    }
    if (tid == 0)
        out[0] = sh[0] / (float)(Bn * Nn);  // (sum_rows + sum_cols) / (B*G)
}

extern "C" void kernel_launch(void* const* d_in, const int* in_sizes, int n_in,
                              void* d_out, int out_size) {
    const float* src = (const float*)d_in[0];  // (4, 8192, 3) fp32
    const float* tgt = (const float*)d_in[1];  // (4, 8192, 3) fp32
    float* out = (float*)d_out;

    dim3 grid(NBX, NBY, Bn);  // (32, 8, 4) = 1024 blocks
    chamfer_main<<<grid, T>>>(src, tgt);
    reduce_partials<<<256, 256>>>();
    final_sum<<<1, 256>>>(out);
}

// round 6
// speedup vs baseline: 1.7615x; 1.0043x over previous
#include <cuda_runtime.h>

// Problem constants (fixed by setup_inputs): B=4, N=M=8192, D=3
constexpr int Bn = 4;
constexpr int Nn = 8192;
constexpr int Mn = 8192;
constexpr int BN = Bn * Nn;  // 32768 (= Bn*Mn too)

constexpr int TC    = 256;   // target chunk staged in shared
constexpr int R     = 8;     // source rows per thread
constexpr int T     = 128;   // threads per block
constexpr int ST    = T * R; // 1024 source rows per block
constexpr int NWARP = T / 32;
constexpr int NBX   = Mn / TC;  // 32 target chunks
constexpr int NBY   = Nn / ST;  // 8 source tiles

// Partial-min scratch (written unconditionally every call -> no init needed)
__device__ float g_rowp[NBX * BN];   // [bx][b*Nn+row] : row min of d2 over chunk bx
__device__ float g_colp[NBY * BN];   // [by][b*Mn+col] : col min of d2 over tile by
__device__ float g_bsum[256];        // per-block partial sums from reduce stage

// FFMA with immediate multiplier 1.0 -> rt=1 imm-form, not demotable to FADD
__device__ __forceinline__ float fma1(float a, float c) {
    float d; asm("fma.rn.f32 %0, %1, 0f3F800000, %2;" : "=f"(d) : "f"(a), "f"(c));
    return d;
}

__global__ __launch_bounds__(T, 7)   // 7*148 >= 1024 blocks: one wave
void chamfer_main(const float* __restrict__ src, const float* __restrict__ tgt) {
    __shared__ float4   tsh[TC];          // target x,y,z,|t|^2
    __shared__ unsigned scolw[NWARP][TC]; // per-warp column min (raw bits, nonneg)

    const int tid  = threadIdx.x;
    const int lane = tid & 31;
    const int w    = tid >> 5;
    const int bx   = blockIdx.x;
    const int by   = blockIdx.y;
    const int b    = blockIdx.z;
    const int s0   = by * ST;
    const int t0   = bx * TC;

    // Stage target chunk into shared (x, y, z, |t|^2)
    for (int i = tid; i < TC; i += T) {
        const float* p = tgt + ((size_t)b * Mn + t0 + i) * 3;
        float x = p[0], y = p[1], z = p[2];
        tsh[i] = make_float4(x, y, z, fmaf(x, x, fmaf(y, y, z * z)));
    }

    // Source rows: NEGATED-DOUBLED coords so the dot chain seeds with t.w
    float sxn[R], syn[R], szn[R], sqs[R], flmin[R];
    const float INF = __int_as_float(0x7f800000);
#pragma unroll
    for (int r = 0; r < R; r++) {
        int row = s0 + tid + r * T;
        const float* p = src + ((size_t)b * Nn + row) * 3;
        float x = p[0], y = p[1], z = p[2];
        sxn[r] = -2.0f * x; syn[r] = -2.0f * y; szn[r] = -2.0f * z;
        sqs[r] = fmaf(x, x, fmaf(y, y, z * z));
        flmin[r] = INF;   // min over j of d2 -> row partial, directly
    }
    __syncthreads();

    // Main sweep. Heavy unroll: all smem addresses become base+immediate,
    // killing per-j IADD3/branch overhead on the alu pipe.
#pragma unroll 16
    for (int j = 0; j < TC; j++) {
        float4 t = tsh[j];  // broadcast LDS.128, conflict-free
        float fl[R];
#pragma unroll
        for (int r = 0; r < R; r++) {
            float e = fmaf(sxn[r], t.x, t.w);   // FFMA rt=2
            e = fmaf(syn[r], t.y, e);           // FFMA rt=2
            e = fmaf(szn[r], t.z, e);           // FFMA rt=2   e = |t|^2 - 2c
            fl[r] = fma1(e, sqs[r]);            // FFMA-imm rt=1: d2 = e + |s|^2
            flmin[r] = fminf(flmin[r], fl[r]);  // FMNMX (alu): row-min of d2
        }
        // Tree-min over this thread's 8 rows (alu pipe) -> column candidate
#pragma unroll
        for (int s = R / 2; s > 0; s >>= 1)
#pragma unroll
            for (int r = 0; r < s; r++) fl[r] = fminf(fl[r], fl[r + s]);
        // Clamp tiny negative rounding artifacts -> raw bits order-preserving
        unsigned k = __reduce_min_sync(0xffffffffu,
                                       __float_as_uint(fmaxf(fl[0], 0.0f)));
        if (lane == 0) scolw[w][j] = k;
    }
    __syncthreads();

    // Column partials: min of d2 over this block's 1024 rows
    for (int j = tid; j < TC; j += T) {
        unsigned m = min(min(scolw[0][j], scolw[1][j]),
                         min(scolw[2][j], scolw[3][j]));
        g_colp[by * BN + b * Mn + t0 + j] = __uint_as_float(m);
    }
    // Row partials: flmin IS the row d2 min for this chunk (coalesced)
#pragma unroll
    for (int r = 0; r < R; r++)
        g_rowp[bx * BN + b * Nn + s0 + tid + r * T] = flmin[r];
}

// Stage 2: blocks 0..127 reduce rows, 128..255 reduce cols. Fixed-order sums.
__global__ void reduce_partials() {
    __shared__ float sh[256];
    const int tid = threadIdx.x;
    const int blk = blockIdx.x;
    float s;
    if (blk < 128) {
        int gr = blk * 256 + tid;  // one row per thread (128*256 = 32768)
        float m = g_rowp[gr];
#pragma unroll
        for (int k = 1; k < NBX; k++) m = fminf(m, g_rowp[k * BN + gr]);
        s = m;
    } else {
        int gc = (blk - 128) * 256 + tid;
        float m = g_colp[gc];
#pragma unroll
        for (int k = 1; k < NBY; k++) m = fminf(m, g_colp[k * BN + gc]);
        s = m;
    }
    sh[tid] = s;
    __syncthreads();
#pragma unroll
    for (int st = 128; st > 0; st >>= 1) {
        if (tid < st) sh[tid] += sh[tid + st];
        __syncthreads();
    }
    if (tid == 0) g_bsum[blk] = sh[0];
}

__global__ void final_sum(float* out) {
    __shared__ float sh[256];
    int tid = threadIdx.x;
    sh[tid] = g_bsum[tid];
    __syncthreads();
#pragma unroll
    for (int st = 128; st > 0; st >>= 1) {
        if (tid < st) sh[tid] += sh[tid + st];
        __syncthreads();
    }
    if (tid == 0)
        out[0] = sh[0] / (float)(Bn * Nn);  // (sum_rows + sum_cols) / (B*G)
}

extern "C" void kernel_launch(void* const* d_in, const int* in_sizes, int n_in,
                              void* d_out, int out_size) {
    const float* src = (const float*)d_in[0];  // (4, 8192, 3) fp32
    const float* tgt = (const float*)d_in[1];  // (4, 8192, 3) fp32
    float* out = (float*)d_out;

    dim3 grid(NBX, NBY, Bn);  // (32, 8, 4) = 1024 blocks
    chamfer_main<<<grid, T>>>(src, tgt);
    reduce_partials<<<256, 256>>>();
    final_sum<<<1, 256>>>(out);
}